// round 1
// baseline (speedup 1.0000x reference)
#include <cuda_runtime.h>

#define B_ 16
#define R_ 1024
#define T_ 512
#define D_ 1024
#define H_ 1024

// Scratch (device globals — no allocations allowed)
__device__ float g_Rproj[(size_t)B_ * R_ * H_];   // 64 MB
__device__ float g_Qproj[(size_t)B_ * T_ * H_];   // 32 MB
__device__ float g_scores[(size_t)B_ * R_ * T_];  // 32 MB

// ---------------------------------------------------------------------------
// Generic NN SGEMM with bias:  C[M,N] = A[M,K] @ W[K,N] + bias[N]
// 128x128 block tile, BK=8, 256 threads, 8x8 register microtile.
// M,N,K all multiples of 128/8 for this problem — no bounds checks.
// ---------------------------------------------------------------------------
__global__ void __launch_bounds__(256) sgemm_nn_bias(
    const float* __restrict__ A, const float* __restrict__ W,
    const float* __restrict__ bias, float* __restrict__ C,
    int M, int N, int K)
{
    const int BM = 128, BN = 128, BK = 8;
    __shared__ float As[BK][BM];
    __shared__ float Bs[BK][BN];

    int tid = threadIdx.x;
    int tn = tid & 15;        // 16 col groups
    int tm = tid >> 4;        // 16 row groups

    size_t aBase = (size_t)blockIdx.y * BM * K;
    size_t bCol  = (size_t)blockIdx.x * BN;

    float acc[8][8] = {};

    int la  = tid * 4;        // 0..1023
    int lar = la >> 3;        // A tile row 0..127
    int lak = la & 7;         // A tile k   0 or 4
    int lbk = la >> 7;        // B tile k   0..7
    int lbc = la & 127;       // B tile col

    for (int k0 = 0; k0 < K; k0 += BK) {
        float4 av = *reinterpret_cast<const float4*>(A + aBase + (size_t)lar * K + k0 + lak);
        As[lak + 0][lar] = av.x; As[lak + 1][lar] = av.y;
        As[lak + 2][lar] = av.z; As[lak + 3][lar] = av.w;
        float4 bv = *reinterpret_cast<const float4*>(W + (size_t)(k0 + lbk) * N + bCol + lbc);
        *reinterpret_cast<float4*>(&Bs[lbk][lbc]) = bv;
        __syncthreads();

        #pragma unroll
        for (int kk = 0; kk < BK; kk++) {
            float a[8], b[8];
            #pragma unroll
            for (int i = 0; i < 8; i++) a[i] = As[kk][tm * 8 + i];
            #pragma unroll
            for (int j = 0; j < 8; j++) b[j] = Bs[kk][tn * 8 + j];
            #pragma unroll
            for (int i = 0; i < 8; i++)
                #pragma unroll
                for (int j = 0; j < 8; j++)
                    acc[i][j] = fmaf(a[i], b[j], acc[i][j]);
        }
        __syncthreads();
    }

    size_t row0 = (size_t)blockIdx.y * BM + tm * 8;
    int    col0 = blockIdx.x * BN + tn * 8;
    #pragma unroll
    for (int i = 0; i < 8; i++) {
        #pragma unroll
        for (int j = 0; j < 8; j += 4) {
            float4 v;
            v.x = acc[i][j + 0] + bias[col0 + j + 0];
            v.y = acc[i][j + 1] + bias[col0 + j + 1];
            v.z = acc[i][j + 2] + bias[col0 + j + 2];
            v.w = acc[i][j + 3] + bias[col0 + j + 3];
            *reinterpret_cast<float4*>(C + (row0 + i) * N + col0 + j) = v;
        }
    }
}

// ---------------------------------------------------------------------------
// Batched NT GEMM:  S[b,r,t] = sum_h Rp[b,r,h] * Qp[b,t,h]
// Both operands K-major (H contiguous). 128x128x8 tiles.
// grid: (T/128, R/128, B)
// ---------------------------------------------------------------------------
__global__ void __launch_bounds__(256) sgemm_nt_scores(
    const float* __restrict__ Rp, const float* __restrict__ Qp,
    float* __restrict__ S)
{
    const int BM = 128, BN = 128, BK = 8;
    __shared__ float As[BK][BM];
    __shared__ float Bs[BK][BN];

    int b = blockIdx.z;
    const float* A = Rp + (size_t)b * R_ * H_;
    const float* Bq = Qp + (size_t)b * T_ * H_;

    int tid = threadIdx.x;
    int tn = tid & 15;
    int tm = tid >> 4;

    float acc[8][8] = {};

    int la = tid * 4;
    int lr = la >> 3;   // 0..127 (tile row for both operands)
    int lk = la & 7;    // 0 or 4

    size_t aRow0 = (size_t)blockIdx.y * BM;
    size_t bRow0 = (size_t)blockIdx.x * BN;

    for (int k0 = 0; k0 < H_; k0 += BK) {
        float4 av = *reinterpret_cast<const float4*>(A + (aRow0 + lr) * H_ + k0 + lk);
        As[lk + 0][lr] = av.x; As[lk + 1][lr] = av.y;
        As[lk + 2][lr] = av.z; As[lk + 3][lr] = av.w;
        float4 bv = *reinterpret_cast<const float4*>(Bq + (bRow0 + lr) * H_ + k0 + lk);
        Bs[lk + 0][lr] = bv.x; Bs[lk + 1][lr] = bv.y;
        Bs[lk + 2][lr] = bv.z; Bs[lk + 3][lr] = bv.w;
        __syncthreads();

        #pragma unroll
        for (int kk = 0; kk < BK; kk++) {
            float a[8], bb[8];
            #pragma unroll
            for (int i = 0; i < 8; i++) a[i] = As[kk][tm * 8 + i];
            #pragma unroll
            for (int j = 0; j < 8; j++) bb[j] = Bs[kk][tn * 8 + j];
            #pragma unroll
            for (int i = 0; i < 8; i++)
                #pragma unroll
                for (int j = 0; j < 8; j++)
                    acc[i][j] = fmaf(a[i], bb[j], acc[i][j]);
        }
        __syncthreads();
    }

    size_t r0 = (size_t)blockIdx.y * BM + tm * 8;
    int    t0 = blockIdx.x * BN + tn * 8;
    #pragma unroll
    for (int i = 0; i < 8; i++) {
        #pragma unroll
        for (int j = 0; j < 8; j += 4) {
            float4 v;
            v.x = acc[i][j + 0]; v.y = acc[i][j + 1];
            v.z = acc[i][j + 2]; v.w = acc[i][j + 3];
            *reinterpret_cast<float4*>(S + ((size_t)b * R_ + r0 + i) * T_ + t0 + j) = v;
        }
    }
}

// ---------------------------------------------------------------------------
// In-place row softmax over T=512. One CTA (256 threads) per (b,r) row.
// ---------------------------------------------------------------------------
__global__ void __launch_bounds__(256) softmax_rows(float* __restrict__ S)
{
    float* row = S + (size_t)blockIdx.x * T_;
    int t = threadIdx.x;
    float v0 = row[t];
    float v1 = row[t + 256];

    __shared__ float red[8];

    float m = fmaxf(v0, v1);
    #pragma unroll
    for (int o = 16; o; o >>= 1) m = fmaxf(m, __shfl_xor_sync(0xffffffffu, m, o));
    if ((t & 31) == 0) red[t >> 5] = m;
    __syncthreads();
    if (t == 0) {
        float x = red[0];
        #pragma unroll
        for (int i = 1; i < 8; i++) x = fmaxf(x, red[i]);
        red[0] = x;
    }
    __syncthreads();
    m = red[0];

    float e0 = expf(v0 - m);
    float e1 = expf(v1 - m);
    float s = e0 + e1;
    #pragma unroll
    for (int o = 16; o; o >>= 1) s += __shfl_xor_sync(0xffffffffu, s, o);
    __syncthreads();                 // done reading red[0]
    if ((t & 31) == 0) red[t >> 5] = s;
    __syncthreads();
    if (t == 0) {
        float x = 0.f;
        #pragma unroll
        for (int i = 0; i < 8; i++) x += red[i];
        red[0] = x;
    }
    __syncthreads();
    float inv = 1.0f / red[0];
    row[t]       = e0 * inv;
    row[t + 256] = e1 * inv;
}

// ---------------------------------------------------------------------------
// Fused: attended[b,r,:] = attn[b,r,:] @ query_embs[b,:,:]
//        out[b,r] = sum_d rf*Ws0 + att*Ws1 + rf*att*Ws2  (+ bs)
// One CTA handles 16 r-rows. attn tile cached in smem (padded vs conflicts),
// query_embs streamed in [16 t x 128 d] tiles (fits in L2 across CTAs).
// grid: (R/16, B), 256 threads; thread = (tm = tid/16 row, tn = tid%16 colgrp)
// ---------------------------------------------------------------------------
__global__ void __launch_bounds__(256) attend_final(
    const float* __restrict__ attn,    // g_scores post-softmax [B,R,T]
    const float* __restrict__ Qe,      // raw query_embs [B,T,D]
    const float* __restrict__ Rf,      // region_feats [B,R,D]
    const float* __restrict__ Ws,      // [3D]
    const float* __restrict__ bs,      // [1]
    float* __restrict__ out)           // [B,R]
{
    const int RB = 16, DCH = 128, TK = 16;
    __shared__ float attn_s[RB][T_ + 1];     // pad: kill stride-512 conflicts
    __shared__ float qe_s[TK][DCH];

    int b  = blockIdx.y;
    int r0 = blockIdx.x * RB;
    int tid = threadIdx.x;
    int tm = tid >> 4;     // 0..15 (row)
    int tn = tid & 15;     // 0..15 (8-wide d-col group)

    // Load attn block [16 x 512]
    const float* abase = attn + ((size_t)b * R_ + r0) * T_;
    for (int i = tid * 4; i < RB * T_; i += 256 * 4) {
        int row = i >> 9;
        int col = i & 511;
        float4 v = *reinterpret_cast<const float4*>(abase + (size_t)row * T_ + col);
        attn_s[row][col + 0] = v.x; attn_s[row][col + 1] = v.y;
        attn_s[row][col + 2] = v.z; attn_s[row][col + 3] = v.w;
    }
    __syncthreads();

    float p = 0.0f;

    for (int d0 = 0; d0 < D_; d0 += DCH) {
        float acc[8] = {};
        for (int t0 = 0; t0 < T_; t0 += TK) {
            __syncthreads();   // previous tile fully consumed
            // load Qe tile [TK x DCH] : 2048 elems, 2 float4 per thread
            #pragma unroll
            for (int u = 0; u < 2; u++) {
                int idx = tid * 4 + u * 1024;
                int tt = idx >> 7;
                int dd = idx & 127;
                float4 v = *reinterpret_cast<const float4*>(
                    Qe + ((size_t)b * T_ + t0 + tt) * D_ + d0 + dd);
                *reinterpret_cast<float4*>(&qe_s[tt][dd]) = v;
            }
            __syncthreads();
            #pragma unroll
            for (int kt = 0; kt < TK; kt++) {
                float av = attn_s[tm][t0 + kt];
                #pragma unroll
                for (int j = 0; j < 8; j++)
                    acc[j] = fmaf(av, qe_s[kt][tn * 8 + j], acc[j]);
            }
        }
        // epilogue for this d chunk
        int r = r0 + tm;
        int dbase = d0 + tn * 8;
        const float* rf = Rf + ((size_t)b * R_ + r) * D_ + dbase;
        #pragma unroll
        for (int j = 0; j < 8; j++) {
            int d = dbase + j;
            float rfv = rf[j];
            float at  = acc[j];
            p = fmaf(rfv, Ws[d], p);
            p = fmaf(at,  Ws[D_ + d], p);
            p = fmaf(rfv * at, Ws[2 * D_ + d], p);
        }
    }

    // reduce p across the 16 threads sharing one row (consecutive lanes)
    #pragma unroll
    for (int o = 8; o; o >>= 1) p += __shfl_down_sync(0xffffffffu, p, o, 16);
    if (tn == 0) out[(size_t)b * R_ + r0 + tm] = p + bs[0];
}

// ---------------------------------------------------------------------------
extern "C" void kernel_launch(void* const* d_in, const int* in_sizes, int n_in,
                              void* d_out, int out_size)
{
    const float* region = (const float*)d_in[0];   // [B,R,D]
    const float* query  = (const float*)d_in[1];   // [B,T,D]
    const float* Wr     = (const float*)d_in[2];   // [D,H]
    const float* br     = (const float*)d_in[3];   // [H]
    const float* Wq     = (const float*)d_in[4];   // [D,H]
    const float* bq     = (const float*)d_in[5];   // [H]
    const float* Ws     = (const float*)d_in[6];   // [3D,1]
    const float* bs     = (const float*)d_in[7];   // [1]
    float* out = (float*)d_out;                    // [B,R]

    float *Rp, *Qp, *Sc;
    cudaGetSymbolAddress((void**)&Rp, g_Rproj);
    cudaGetSymbolAddress((void**)&Qp, g_Qproj);
    cudaGetSymbolAddress((void**)&Sc, g_scores);

    // 1) projections
    sgemm_nn_bias<<<dim3(H_ / 128, (B_ * R_) / 128), 256>>>(region, Wr, br, Rp,
                                                            B_ * R_, H_, D_);
    sgemm_nn_bias<<<dim3(H_ / 128, (B_ * T_) / 128), 256>>>(query, Wq, bq, Qp,
                                                            B_ * T_, H_, D_);
    // 2) scores
    sgemm_nt_scores<<<dim3(T_ / 128, R_ / 128, B_), 256>>>(Rp, Qp, Sc);
    // 3) softmax (in-place)
    softmax_rows<<<B_ * R_, 256>>>(Sc);
    // 4) fused attended + final projection
    attend_final<<<dim3(R_ / 16, B_), 256>>>(Sc, query, region, Ws, bs, out);
}

// round 3
// speedup vs baseline: 4.5380x; 4.5380x over previous
#include <cuda_runtime.h>
#include <cuda_bf16.h>

#define BB 16
#define RR 1024
#define TT 512
#define DD 1024
#define HH 1024

// ---------------------------------------------------------------------------
// Scratch (device globals — allocations are forbidden)
// ---------------------------------------------------------------------------
__device__ __nv_bfloat16 g_WrT_h[HH * DD], g_WrT_l[HH * DD];
__device__ __nv_bfloat16 g_WqT_h[HH * DD], g_WqT_l[HH * DD];
__device__ __nv_bfloat16 g_reg_h[(size_t)BB * RR * DD], g_reg_l[(size_t)BB * RR * DD];
__device__ __nv_bfloat16 g_qry_h[(size_t)BB * TT * DD], g_qry_l[(size_t)BB * TT * DD];
__device__ __nv_bfloat16 g_Rp_h[(size_t)BB * RR * HH], g_Rp_l[(size_t)BB * RR * HH];
__device__ __nv_bfloat16 g_Qp_h[(size_t)BB * TT * HH], g_Qp_l[(size_t)BB * TT * HH];
__device__ float         g_scores[(size_t)BB * RR * TT];
__device__ __nv_bfloat16 g_attn_h[(size_t)BB * RR * TT], g_attn_l[(size_t)BB * RR * TT];
__device__ __nv_bfloat16 g_qeT_h[(size_t)BB * DD * TT], g_qeT_l[(size_t)BB * DD * TT];
__device__ float         g_att[(size_t)BB * RR * DD];

// ---------------------------------------------------------------------------
// PTX helpers (sm_80-level features only: ldmatrix, cp.async, mma.sync)
// ---------------------------------------------------------------------------
__device__ __forceinline__ unsigned smem_u32(const void* p) {
    unsigned a;
    asm("{ .reg .u64 t; cvta.to.shared.u64 t, %1; cvt.u32.u64 %0, t; }" : "=r"(a) : "l"(p));
    return a;
}

#define CP_ASYNC16(dst, src) \
    asm volatile("cp.async.cg.shared.global [%0], [%1], 16;" :: "r"(dst), "l"(src))
#define CP_COMMIT() asm volatile("cp.async.commit_group;" ::: "memory")
#define CP_WAIT0()  asm volatile("cp.async.wait_group 0;" ::: "memory")
#define CP_WAIT1()  asm volatile("cp.async.wait_group 1;" ::: "memory")

__device__ __forceinline__ void ldsm4(unsigned* r, unsigned addr) {
    asm volatile("ldmatrix.sync.aligned.m8n8.x4.shared.b16 {%0,%1,%2,%3}, [%4];"
                 : "=r"(r[0]), "=r"(r[1]), "=r"(r[2]), "=r"(r[3]) : "r"(addr));
}

__device__ __forceinline__ void mma_bf16(float* c, const unsigned* a, const unsigned* b) {
    asm volatile(
        "mma.sync.aligned.m16n8k16.row.col.f32.bf16.bf16.f32 "
        "{%0,%1,%2,%3}, {%4,%5,%6,%7}, {%8,%9}, {%0,%1,%2,%3};"
        : "+f"(c[0]), "+f"(c[1]), "+f"(c[2]), "+f"(c[3])
        : "r"(a[0]), "r"(a[1]), "r"(a[2]), "r"(a[3]), "r"(b[0]), "r"(b[1]));
}

__device__ __forceinline__ unsigned swz(unsigned off) {
    return off ^ ((off >> 3) & 0x70);
}

// ---------------------------------------------------------------------------
// Split-bf16 tensor-core GEMM:  C[m,n] = sum_k A[m,k]*B[n,k]  (+bias)
// A = Ah+Al, B = Bh+Bl (bf16 pairs). TERMS=4: hh+hl+lh+ll; TERMS=3: drop ll.
// CTA tile 128x128, K chunks of 64 bf16 (=128B rows, SW128), double-buffered
// cp.async. 8 warps: 4(M) x 2(N), warp tile 32x64 -> 2x8 m16n8k16 frags.
// SPLIT_OUT: write hi/lo bf16 (+bias) instead of fp32.
// ---------------------------------------------------------------------------
template <int TERMS, bool SPLIT_OUT>
__global__ void __launch_bounds__(256) gemm_mma(
    const __nv_bfloat16* __restrict__ A0, const __nv_bfloat16* __restrict__ A1,
    const __nv_bfloat16* __restrict__ B0, const __nv_bfloat16* __restrict__ B1,
    float* __restrict__ Cf, __nv_bfloat16* __restrict__ Ch,
    __nv_bfloat16* __restrict__ Cl, const float* __restrict__ bias,
    int K, size_t sA, size_t sB, size_t sC, int ldc)
{
    constexpr unsigned TILE = 128 * 64 * 2;   // 16 KB per operand tile
    constexpr unsigned STAGE = 4 * TILE;      // Ah, Al, Bh, Bl

    extern __shared__ char smem[];
    const unsigned sbase = smem_u32(smem);

    const int tid = threadIdx.x;
    const int lid = tid & 31;
    const int wid = tid >> 5;
    const int wm = wid & 3;        // M slab (32 rows)
    const int wn = wid >> 2;       // N slab (64 cols)

    const size_t zb = blockIdx.z;
    const __nv_bfloat16* AP[2] = { A0 + zb * sA, A1 + zb * sA };
    const __nv_bfloat16* BP[2] = { B0 + zb * sB, B1 + zb * sB };
    const size_t rm0 = (size_t)blockIdx.y * 128;
    const size_t rn0 = (size_t)blockIdx.x * 128;
    const int NC = K >> 6;

    float c[2][8][4] = {};

    // ldmatrix per-lane address components
    const int al_r  = lid & 15;          // A: row within 16-row frag
    const int al_k  = (lid >> 4) & 1;    // A: 16B chunk select (k 0-7 / 8-15)
    const int bl_r  = (lid & 7) + ((lid >> 4) << 3);  // B: row (n) 0..15
    const int bl_k  = (lid >> 3) & 1;    // B: 16B chunk select

    auto load_stage = [&](int st, int ck) {
        const unsigned sdst = sbase + (unsigned)st * STAGE;
        const int k0 = ck << 6;
        #pragma unroll
        for (int t4 = 0; t4 < 4; t4++) {
            const __nv_bfloat16* src = (t4 < 2) ? AP[t4] : BP[t4 - 2];
            const size_t r0 = (t4 < 2) ? rm0 : rn0;
            #pragma unroll
            for (int i = 0; i < 4; i++) {
                int idx = i * 256 + tid;
                int row = idx >> 3, g = idx & 7;
                const __nv_bfloat16* gs = src + (r0 + row) * (size_t)K + k0 + g * 8;
                unsigned d = sdst + (unsigned)t4 * TILE + swz((unsigned)(row * 128 + g * 16));
                CP_ASYNC16(d, gs);
            }
        }
    };

    constexpr int PI[4] = {0, 0, 1, 1};
    constexpr int PJ[4] = {0, 1, 0, 1};

    load_stage(0, 0);
    CP_COMMIT();

    for (int ck = 0; ck < NC; ck++) {
        if (ck + 1 < NC) {
            load_stage((ck + 1) & 1, ck + 1);
            CP_COMMIT();
            CP_WAIT1();
        } else {
            CP_WAIT0();
        }
        __syncthreads();

        const unsigned sb2 = sbase + (unsigned)(ck & 1) * STAGE;
        #pragma unroll
        for (int ks = 0; ks < 4; ks++) {
            unsigned af[2][2][4];
            unsigned bf[2][8][2];
            #pragma unroll
            for (int sp = 0; sp < 2; sp++) {
                #pragma unroll
                for (int mt = 0; mt < 2; mt++) {
                    unsigned addr = sb2 + (unsigned)sp * TILE +
                        swz((unsigned)((wm * 32 + mt * 16 + al_r) * 128 + ks * 32 + al_k * 16));
                    ldsm4(af[sp][mt], addr);
                }
                #pragma unroll
                for (int np = 0; np < 4; np++) {
                    unsigned r[4];
                    unsigned addr = sb2 + (unsigned)(2 + sp) * TILE +
                        swz((unsigned)((wn * 64 + np * 16 + bl_r) * 128 + ks * 32 + bl_k * 16));
                    ldsm4(r, addr);
                    bf[sp][2 * np][0] = r[0]; bf[sp][2 * np][1] = r[1];
                    bf[sp][2 * np + 1][0] = r[2]; bf[sp][2 * np + 1][1] = r[3];
                }
            }
            #pragma unroll
            for (int tm = 0; tm < TERMS; tm++) {
                const int i = PI[tm], j = PJ[tm];
                #pragma unroll
                for (int mt = 0; mt < 2; mt++)
                    #pragma unroll
                    for (int nt = 0; nt < 8; nt++)
                        mma_bf16(c[mt][nt], af[i][mt], bf[j][nt]);
            }
        }
        __syncthreads();
    }

    // Epilogue: register c-frags -> gmem
    const int qr = lid >> 2;
    const int qc = (lid & 3) * 2;
    #pragma unroll
    for (int mt = 0; mt < 2; mt++) {
        #pragma unroll
        for (int nt = 0; nt < 8; nt++) {
            size_t gr = rm0 + wm * 32 + mt * 16 + qr;
            int gc = (int)rn0 + wn * 64 + nt * 8 + qc;
            if (SPLIT_OUT) {
                float b0 = bias[gc], b1 = bias[gc + 1];
                #pragma unroll
                for (int half = 0; half < 2; half++) {
                    float v0 = c[mt][nt][2 * half + 0] + b0;
                    float v1 = c[mt][nt][2 * half + 1] + b1;
                    size_t o = zb * sC + (gr + half * 8) * (size_t)ldc + gc;
                    __nv_bfloat162 hv, lv;
                    hv.x = __float2bfloat16(v0);
                    hv.y = __float2bfloat16(v1);
                    lv.x = __float2bfloat16(v0 - __bfloat162float(hv.x));
                    lv.y = __float2bfloat16(v1 - __bfloat162float(hv.y));
                    *reinterpret_cast<__nv_bfloat162*>(Ch + o) = hv;
                    *reinterpret_cast<__nv_bfloat162*>(Cl + o) = lv;
                }
            } else {
                #pragma unroll
                for (int half = 0; half < 2; half++) {
                    size_t o = zb * sC + (gr + half * 8) * (size_t)ldc + gc;
                    float2 v = make_float2(c[mt][nt][2 * half], c[mt][nt][2 * half + 1]);
                    *reinterpret_cast<float2*>(Cf + o) = v;
                }
            }
        }
    }
}

// ---------------------------------------------------------------------------
// fp32 -> 2-way bf16 split (elementwise, vectorized)
// ---------------------------------------------------------------------------
__global__ void __launch_bounds__(256) split2_k(
    const float4* __restrict__ x, __nv_bfloat16* __restrict__ h,
    __nv_bfloat16* __restrict__ l, int n4)
{
    for (int i = blockIdx.x * blockDim.x + threadIdx.x; i < n4;
         i += gridDim.x * blockDim.x) {
        float4 v = x[i];
        float a[4] = {v.x, v.y, v.z, v.w};
        __nv_bfloat16 hh[4], ll[4];
        #pragma unroll
        for (int k = 0; k < 4; k++) {
            hh[k] = __float2bfloat16(a[k]);
            ll[k] = __float2bfloat16(a[k] - __bfloat162float(hh[k]));
        }
        __nv_bfloat162 p0, p1;
        p0.x = hh[0]; p0.y = hh[1]; p1.x = hh[2]; p1.y = hh[3];
        reinterpret_cast<__nv_bfloat162*>(h)[2 * i] = p0;
        reinterpret_cast<__nv_bfloat162*>(h)[2 * i + 1] = p1;
        p0.x = ll[0]; p0.y = ll[1]; p1.x = ll[2]; p1.y = ll[3];
        reinterpret_cast<__nv_bfloat162*>(l)[2 * i] = p0;
        reinterpret_cast<__nv_bfloat162*>(l)[2 * i + 1] = p1;
    }
}

// ---------------------------------------------------------------------------
// Batched transpose + 2-way split: src[b,rows,cols] -> dst[b,cols,rows]
// ---------------------------------------------------------------------------
__global__ void tsplit2_k(const float* __restrict__ src,
                          __nv_bfloat16* __restrict__ d0,
                          __nv_bfloat16* __restrict__ d1, int rows, int cols)
{
    __shared__ float tile[32][33];
    int b = blockIdx.z;
    const float* s = src + (size_t)b * rows * cols;
    int c0 = blockIdx.x * 32, r0 = blockIdx.y * 32;
    int tx = threadIdx.x, ty = threadIdx.y;
    #pragma unroll
    for (int k = 0; k < 32; k += 8)
        tile[ty + k][tx] = s[(size_t)(r0 + ty + k) * cols + c0 + tx];
    __syncthreads();
    size_t dbase = (size_t)b * rows * cols;
    #pragma unroll
    for (int k = 0; k < 32; k += 8) {
        int oc = c0 + ty + k;
        float v = tile[tx][ty + k];
        size_t o = dbase + (size_t)oc * rows + r0 + tx;
        __nv_bfloat16 h = __float2bfloat16(v);
        d0[o] = h;
        d1[o] = __float2bfloat16(v - __bfloat162float(h));
    }
}

// ---------------------------------------------------------------------------
// Row softmax over T=512 + 2-way bf16 split of the result
// ---------------------------------------------------------------------------
__global__ void __launch_bounds__(256) softmax_split(
    const float* __restrict__ S, __nv_bfloat16* __restrict__ Ah,
    __nv_bfloat16* __restrict__ Al)
{
    const float* row = S + (size_t)blockIdx.x * TT;
    int t = threadIdx.x;
    float v0 = row[t];
    float v1 = row[t + 256];

    __shared__ float red[8];

    float m = fmaxf(v0, v1);
    #pragma unroll
    for (int o = 16; o; o >>= 1) m = fmaxf(m, __shfl_xor_sync(0xffffffffu, m, o));
    if ((t & 31) == 0) red[t >> 5] = m;
    __syncthreads();
    if (t == 0) {
        float x = red[0];
        #pragma unroll
        for (int i = 1; i < 8; i++) x = fmaxf(x, red[i]);
        red[0] = x;
    }
    __syncthreads();
    m = red[0];

    float e0 = expf(v0 - m);
    float e1 = expf(v1 - m);
    float s = e0 + e1;
    #pragma unroll
    for (int o = 16; o; o >>= 1) s += __shfl_xor_sync(0xffffffffu, s, o);
    __syncthreads();
    if ((t & 31) == 0) red[t >> 5] = s;
    __syncthreads();
    if (t == 0) {
        float x = 0.f;
        #pragma unroll
        for (int i = 0; i < 8; i++) x += red[i];
        red[0] = x;
    }
    __syncthreads();
    float inv = 1.0f / red[0];
    size_t base = (size_t)blockIdx.x * TT;

    float a0 = e0 * inv;
    __nv_bfloat16 h0 = __float2bfloat16(a0);
    Ah[base + t] = h0;
    Al[base + t] = __float2bfloat16(a0 - __bfloat162float(h0));

    float a1 = e1 * inv;
    __nv_bfloat16 h1 = __float2bfloat16(a1);
    Ah[base + t + 256] = h1;
    Al[base + t + 256] = __float2bfloat16(a1 - __bfloat162float(h1));
}

// ---------------------------------------------------------------------------
// Final: out[b,r] = sum_d rf*Ws0 + att*Ws1 + rf*att*Ws2  (+bs)
// ---------------------------------------------------------------------------
__global__ void __launch_bounds__(256) final_out(
    const float* __restrict__ rf, const float* __restrict__ att,
    const float* __restrict__ Ws, const float* __restrict__ bs,
    float* __restrict__ out)
{
    size_t row = blockIdx.x;
    const float4* r4 = reinterpret_cast<const float4*>(rf + row * DD);
    const float4* a4 = reinterpret_cast<const float4*>(att + row * DD);
    int t = threadIdx.x;
    float4 rv = r4[t], av = a4[t];
    int d = t * 4;
    float p = 0.f;
    p = fmaf(rv.x, Ws[d + 0], p); p = fmaf(av.x, Ws[DD + d + 0], p); p = fmaf(rv.x * av.x, Ws[2 * DD + d + 0], p);
    p = fmaf(rv.y, Ws[d + 1], p); p = fmaf(av.y, Ws[DD + d + 1], p); p = fmaf(rv.y * av.y, Ws[2 * DD + d + 1], p);
    p = fmaf(rv.z, Ws[d + 2], p); p = fmaf(av.z, Ws[DD + d + 2], p); p = fmaf(rv.z * av.z, Ws[2 * DD + d + 2], p);
    p = fmaf(rv.w, Ws[d + 3], p); p = fmaf(av.w, Ws[DD + d + 3], p); p = fmaf(rv.w * av.w, Ws[2 * DD + d + 3], p);

    __shared__ float red[8];
    #pragma unroll
    for (int o = 16; o; o >>= 1) p += __shfl_xor_sync(0xffffffffu, p, o);
    if ((t & 31) == 0) red[t >> 5] = p;
    __syncthreads();
    if (t == 0) {
        float s = 0.f;
        #pragma unroll
        for (int i = 0; i < 8; i++) s += red[i];
        out[row] = s + bs[0];
    }
}

// ---------------------------------------------------------------------------
extern "C" void kernel_launch(void* const* d_in, const int* in_sizes, int n_in,
                              void* d_out, int out_size)
{
    const float* region = (const float*)d_in[0];
    const float* query  = (const float*)d_in[1];
    const float* Wr     = (const float*)d_in[2];
    const float* br     = (const float*)d_in[3];
    const float* Wq     = (const float*)d_in[4];
    const float* bq     = (const float*)d_in[5];
    const float* Ws     = (const float*)d_in[6];
    const float* bs     = (const float*)d_in[7];
    float* out = (float*)d_out;

    __nv_bfloat16 *WrT_h, *WrT_l, *WqT_h, *WqT_l;
    __nv_bfloat16 *reg_h, *reg_l, *qry_h, *qry_l;
    __nv_bfloat16 *Rp_h, *Rp_l, *Qp_h, *Qp_l, *attn_h, *attn_l, *qeT_h, *qeT_l;
    float *scores, *att;
    cudaGetSymbolAddress((void**)&WrT_h, g_WrT_h);
    cudaGetSymbolAddress((void**)&WrT_l, g_WrT_l);
    cudaGetSymbolAddress((void**)&WqT_h, g_WqT_h);
    cudaGetSymbolAddress((void**)&WqT_l, g_WqT_l);
    cudaGetSymbolAddress((void**)&reg_h, g_reg_h);
    cudaGetSymbolAddress((void**)&reg_l, g_reg_l);
    cudaGetSymbolAddress((void**)&qry_h, g_qry_h);
    cudaGetSymbolAddress((void**)&qry_l, g_qry_l);
    cudaGetSymbolAddress((void**)&Rp_h, g_Rp_h);
    cudaGetSymbolAddress((void**)&Rp_l, g_Rp_l);
    cudaGetSymbolAddress((void**)&Qp_h, g_Qp_h);
    cudaGetSymbolAddress((void**)&Qp_l, g_Qp_l);
    cudaGetSymbolAddress((void**)&scores, g_scores);
    cudaGetSymbolAddress((void**)&attn_h, g_attn_h);
    cudaGetSymbolAddress((void**)&attn_l, g_attn_l);
    cudaGetSymbolAddress((void**)&qeT_h, g_qeT_h);
    cudaGetSymbolAddress((void**)&qeT_l, g_qeT_l);
    cudaGetSymbolAddress((void**)&att, g_att);

    const int SMEM = 2 * 4 * 16384;   // 131072
    cudaFuncSetAttribute(gemm_mma<4, true>,
                         cudaFuncAttributeMaxDynamicSharedMemorySize, SMEM);
    cudaFuncSetAttribute(gemm_mma<3, false>,
                         cudaFuncAttributeMaxDynamicSharedMemorySize, SMEM);

    // 1) weight transposes + splits
    tsplit2_k<<<dim3(HH / 32, DD / 32, 1), dim3(32, 8)>>>(Wr, WrT_h, WrT_l, DD, HH);
    tsplit2_k<<<dim3(HH / 32, DD / 32, 1), dim3(32, 8)>>>(Wq, WqT_h, WqT_l, DD, HH);
    // 2) activation splits
    split2_k<<<2048, 256>>>((const float4*)region, reg_h, reg_l,
                            (int)((size_t)BB * RR * DD / 4));
    split2_k<<<2048, 256>>>((const float4*)query, qry_h, qry_l,
                            (int)((size_t)BB * TT * DD / 4));
    // 3) projections (4-term split, bf16 h/l output, +bias)
    gemm_mma<4, true><<<dim3(HH / 128, (BB * RR) / 128, 1), 256, SMEM>>>(
        reg_h, reg_l, WrT_h, WrT_l, nullptr, Rp_h, Rp_l, br,
        DD, 0, 0, 0, HH);
    gemm_mma<4, true><<<dim3(HH / 128, (BB * TT) / 128, 1), 256, SMEM>>>(
        qry_h, qry_l, WqT_h, WqT_l, nullptr, Qp_h, Qp_l, bq,
        DD, 0, 0, 0, HH);
    // 4) scores (batched NT, 3-term)
    gemm_mma<3, false><<<dim3(TT / 128, RR / 128, BB), 256, SMEM>>>(
        Rp_h, Rp_l, Qp_h, Qp_l, scores, nullptr, nullptr, nullptr,
        HH, (size_t)RR * HH, (size_t)TT * HH, (size_t)RR * TT, TT);
    // 5) softmax + split of attn
    softmax_split<<<BB * RR, 256>>>(scores, attn_h, attn_l);
    // 6) query transpose + split (B operand of attend GEMM)
    tsplit2_k<<<dim3(DD / 32, TT / 32, BB), dim3(32, 8)>>>(query, qeT_h, qeT_l, TT, DD);
    // 7) attended = attn @ query  (batched, 3-term)
    gemm_mma<3, false><<<dim3(DD / 128, RR / 128, BB), 256, SMEM>>>(
        attn_h, attn_l, qeT_h, qeT_l, att, nullptr, nullptr, nullptr,
        TT, (size_t)RR * TT, (size_t)DD * TT, (size_t)RR * DD, DD);
    // 8) final fused elementwise + reduce
    final_out<<<BB * RR, 256>>>(region, att, Ws, bs, out);
}

// round 4
// speedup vs baseline: 5.8264x; 1.2839x over previous
#include <cuda_runtime.h>
#include <cuda_bf16.h>

#define BB 16
#define RR 1024
#define TT 512
#define DD 1024
#define HH 1024

// ---------------------------------------------------------------------------
// Scratch (device globals — allocations are forbidden)
// ---------------------------------------------------------------------------
__device__ __nv_bfloat16 g_Wr_h[DD * HH], g_Wr_l[DD * HH];
__device__ __nv_bfloat16 g_Wq_h[DD * HH], g_Wq_l[DD * HH];
__device__ __nv_bfloat16 g_Mt_h[DD * DD], g_Mt_l[DD * DD];       // Mt[e,d] = sum_h Wq[e,h]Wr[d,h]
__device__ __nv_bfloat16 g_rf_h[(size_t)BB * RR * DD], g_rf_l[(size_t)BB * RR * DD];
__device__ __nv_bfloat16 g_qe_h[(size_t)BB * TT * DD], g_qe_l[(size_t)BB * TT * DD];
__device__ __nv_bfloat16 g_P_h[(size_t)BB * RR * DD], g_P_l[(size_t)BB * RR * DD];
__device__ float         g_scores[(size_t)BB * RR * TT];
__device__ __nv_bfloat16 g_attn_h[(size_t)BB * RR * TT], g_attn_l[(size_t)BB * RR * TT];
__device__ __nv_bfloat16 g_qeT_h[(size_t)BB * DD * TT], g_qeT_l[(size_t)BB * DD * TT];
__device__ float         g_att[(size_t)BB * RR * DD];
__device__ float         g_v[DD];
__device__ float         g_qv[BB * TT];

// ---------------------------------------------------------------------------
// PTX helpers (sm_80-level features only: ldmatrix, cp.async, mma.sync)
// ---------------------------------------------------------------------------
__device__ __forceinline__ unsigned smem_u32(const void* p) {
    unsigned a;
    asm("{ .reg .u64 t; cvta.to.shared.u64 t, %1; cvt.u32.u64 %0, t; }" : "=r"(a) : "l"(p));
    return a;
}

#define CP_ASYNC16(dst, src) \
    asm volatile("cp.async.cg.shared.global [%0], [%1], 16;" :: "r"(dst), "l"(src))
#define CP_COMMIT() asm volatile("cp.async.commit_group;" ::: "memory")
#define CP_WAIT0()  asm volatile("cp.async.wait_group 0;" ::: "memory")
#define CP_WAIT1()  asm volatile("cp.async.wait_group 1;" ::: "memory")

__device__ __forceinline__ void ldsm4(unsigned* r, unsigned addr) {
    asm volatile("ldmatrix.sync.aligned.m8n8.x4.shared.b16 {%0,%1,%2,%3}, [%4];"
                 : "=r"(r[0]), "=r"(r[1]), "=r"(r[2]), "=r"(r[3]) : "r"(addr));
}

__device__ __forceinline__ void mma_bf16(float* c, const unsigned* a, const unsigned* b) {
    asm volatile(
        "mma.sync.aligned.m16n8k16.row.col.f32.bf16.bf16.f32 "
        "{%0,%1,%2,%3}, {%4,%5,%6,%7}, {%8,%9}, {%0,%1,%2,%3};"
        : "+f"(c[0]), "+f"(c[1]), "+f"(c[2]), "+f"(c[3])
        : "r"(a[0]), "r"(a[1]), "r"(a[2]), "r"(a[3]), "r"(b[0]), "r"(b[1]));
}

__device__ __forceinline__ unsigned swz(unsigned off) {
    return off ^ ((off >> 3) & 0x70);
}

// ---------------------------------------------------------------------------
// Split-bf16 tensor-core GEMM:  C[m,n] = sum_k A[m,k]*B[n,k]  (+bias optional)
// 3 terms: hh + hl + lh (ll dropped). CTA tile 128x128, K chunks of 64 bf16
// (SW128), double-buffered cp.async. 8 warps (4M x 2N), warp tile 32x64.
// SPLIT_OUT: write hi/lo bf16 instead of fp32.
// ---------------------------------------------------------------------------
template <bool SPLIT_OUT>
__global__ void __launch_bounds__(256) gemm_mma(
    const __nv_bfloat16* __restrict__ A0, const __nv_bfloat16* __restrict__ A1,
    const __nv_bfloat16* __restrict__ B0, const __nv_bfloat16* __restrict__ B1,
    float* __restrict__ Cf, __nv_bfloat16* __restrict__ Ch,
    __nv_bfloat16* __restrict__ Cl, const float* __restrict__ bias,
    int K, size_t sA, size_t sB, size_t sC, int ldc)
{
    constexpr unsigned TILE = 128 * 64 * 2;   // 16 KB per operand tile
    constexpr unsigned STAGE = 4 * TILE;      // Ah, Al, Bh, Bl

    extern __shared__ char smem[];
    const unsigned sbase = smem_u32(smem);

    const int tid = threadIdx.x;
    const int lid = tid & 31;
    const int wid = tid >> 5;
    const int wm = wid & 3;        // M slab (32 rows)
    const int wn = wid >> 2;       // N slab (64 cols)

    const size_t zb = blockIdx.z;
    const __nv_bfloat16* AP[2] = { A0 + zb * sA, A1 + zb * sA };
    const __nv_bfloat16* BP[2] = { B0 + zb * sB, B1 + zb * sB };
    const size_t rm0 = (size_t)blockIdx.y * 128;
    const size_t rn0 = (size_t)blockIdx.x * 128;
    const int NC = K >> 6;

    float c[2][8][4] = {};

    const int al_r  = lid & 15;
    const int al_k  = (lid >> 4) & 1;
    const int bl_r  = (lid & 7) + ((lid >> 4) << 3);
    const int bl_k  = (lid >> 3) & 1;

    auto load_stage = [&](int st, int ck) {
        const unsigned sdst = sbase + (unsigned)st * STAGE;
        const int k0 = ck << 6;
        #pragma unroll
        for (int t4 = 0; t4 < 4; t4++) {
            const __nv_bfloat16* src = (t4 < 2) ? AP[t4] : BP[t4 - 2];
            const size_t r0 = (t4 < 2) ? rm0 : rn0;
            #pragma unroll
            for (int i = 0; i < 4; i++) {
                int idx = i * 256 + tid;
                int row = idx >> 3, g = idx & 7;
                const __nv_bfloat16* gs = src + (r0 + row) * (size_t)K + k0 + g * 8;
                unsigned d = sdst + (unsigned)t4 * TILE + swz((unsigned)(row * 128 + g * 16));
                CP_ASYNC16(d, gs);
            }
        }
    };

    load_stage(0, 0);
    CP_COMMIT();

    for (int ck = 0; ck < NC; ck++) {
        if (ck + 1 < NC) {
            load_stage((ck + 1) & 1, ck + 1);
            CP_COMMIT();
            CP_WAIT1();
        } else {
            CP_WAIT0();
        }
        __syncthreads();

        const unsigned sb2 = sbase + (unsigned)(ck & 1) * STAGE;
        #pragma unroll
        for (int ks = 0; ks < 4; ks++) {
            unsigned af[2][2][4];
            unsigned bf[2][8][2];
            #pragma unroll
            for (int sp = 0; sp < 2; sp++) {
                #pragma unroll
                for (int mt = 0; mt < 2; mt++) {
                    unsigned addr = sb2 + (unsigned)sp * TILE +
                        swz((unsigned)((wm * 32 + mt * 16 + al_r) * 128 + ks * 32 + al_k * 16));
                    ldsm4(af[sp][mt], addr);
                }
                #pragma unroll
                for (int np = 0; np < 4; np++) {
                    unsigned r[4];
                    unsigned addr = sb2 + (unsigned)(2 + sp) * TILE +
                        swz((unsigned)((wn * 64 + np * 16 + bl_r) * 128 + ks * 32 + bl_k * 16));
                    ldsm4(r, addr);
                    bf[sp][2 * np][0] = r[0]; bf[sp][2 * np][1] = r[1];
                    bf[sp][2 * np + 1][0] = r[2]; bf[sp][2 * np + 1][1] = r[3];
                }
            }
            // 3 terms: hh, hl, lh
            #pragma unroll
            for (int tm = 0; tm < 3; tm++) {
                const int i = (tm == 2) ? 1 : 0;
                const int j = (tm == 1) ? 1 : 0;
                #pragma unroll
                for (int mt = 0; mt < 2; mt++)
                    #pragma unroll
                    for (int nt = 0; nt < 8; nt++)
                        mma_bf16(c[mt][nt], af[i][mt], bf[j][nt]);
            }
        }
        __syncthreads();
    }

    const int qr = lid >> 2;
    const int qc = (lid & 3) * 2;
    #pragma unroll
    for (int mt = 0; mt < 2; mt++) {
        #pragma unroll
        for (int nt = 0; nt < 8; nt++) {
            size_t gr = rm0 + wm * 32 + mt * 16 + qr;
            int gc = (int)rn0 + wn * 64 + nt * 8 + qc;
            if (SPLIT_OUT) {
                float b0 = bias ? bias[gc] : 0.f;
                float b1 = bias ? bias[gc + 1] : 0.f;
                #pragma unroll
                for (int half = 0; half < 2; half++) {
                    float v0 = c[mt][nt][2 * half + 0] + b0;
                    float v1 = c[mt][nt][2 * half + 1] + b1;
                    size_t o = zb * sC + (gr + half * 8) * (size_t)ldc + gc;
                    __nv_bfloat162 hv, lv;
                    hv.x = __float2bfloat16(v0);
                    hv.y = __float2bfloat16(v1);
                    lv.x = __float2bfloat16(v0 - __bfloat162float(hv.x));
                    lv.y = __float2bfloat16(v1 - __bfloat162float(hv.y));
                    *reinterpret_cast<__nv_bfloat162*>(Ch + o) = hv;
                    *reinterpret_cast<__nv_bfloat162*>(Cl + o) = lv;
                }
            } else {
                #pragma unroll
                for (int half = 0; half < 2; half++) {
                    size_t o = zb * sC + (gr + half * 8) * (size_t)ldc + gc;
                    float2 v = make_float2(c[mt][nt][2 * half], c[mt][nt][2 * half + 1]);
                    *reinterpret_cast<float2*>(Cf + o) = v;
                }
            }
        }
    }
}

// ---------------------------------------------------------------------------
// fp32 -> 2-way bf16 split (elementwise, vectorized)
// ---------------------------------------------------------------------------
__global__ void __launch_bounds__(256) split2_k(
    const float4* __restrict__ x, __nv_bfloat16* __restrict__ h,
    __nv_bfloat16* __restrict__ l, int n4)
{
    for (int i = blockIdx.x * blockDim.x + threadIdx.x; i < n4;
         i += gridDim.x * blockDim.x) {
        float4 v = x[i];
        float a[4] = {v.x, v.y, v.z, v.w};
        __nv_bfloat16 hh[4], ll[4];
        #pragma unroll
        for (int k = 0; k < 4; k++) {
            hh[k] = __float2bfloat16(a[k]);
            ll[k] = __float2bfloat16(a[k] - __bfloat162float(hh[k]));
        }
        __nv_bfloat162 p0, p1;
        p0.x = hh[0]; p0.y = hh[1]; p1.x = hh[2]; p1.y = hh[3];
        reinterpret_cast<__nv_bfloat162*>(h)[2 * i] = p0;
        reinterpret_cast<__nv_bfloat162*>(h)[2 * i + 1] = p1;
        p0.x = ll[0]; p0.y = ll[1]; p1.x = ll[2]; p1.y = ll[3];
        reinterpret_cast<__nv_bfloat162*>(l)[2 * i] = p0;
        reinterpret_cast<__nv_bfloat162*>(l)[2 * i + 1] = p1;
    }
}

// ---------------------------------------------------------------------------
// Batched transpose + 2-way split: src[b,rows,cols] -> dst[b,cols,rows]
// ---------------------------------------------------------------------------
__global__ void tsplit2_k(const float* __restrict__ src,
                          __nv_bfloat16* __restrict__ d0,
                          __nv_bfloat16* __restrict__ d1, int rows, int cols)
{
    __shared__ float tile[32][33];
    int b = blockIdx.z;
    const float* s = src + (size_t)b * rows * cols;
    int c0 = blockIdx.x * 32, r0 = blockIdx.y * 32;
    int tx = threadIdx.x, ty = threadIdx.y;
    #pragma unroll
    for (int k = 0; k < 32; k += 8)
        tile[ty + k][tx] = s[(size_t)(r0 + ty + k) * cols + c0 + tx];
    __syncthreads();
    size_t dbase = (size_t)b * rows * cols;
    #pragma unroll
    for (int k = 0; k < 32; k += 8) {
        int oc = c0 + ty + k;
        float v = tile[tx][ty + k];
        size_t o = dbase + (size_t)oc * rows + r0 + tx;
        __nv_bfloat16 h = __float2bfloat16(v);
        d0[o] = h;
        d1[o] = __float2bfloat16(v - __bfloat162float(h));
    }
}

// ---------------------------------------------------------------------------
// v[d] = sum_h Wq[d,h] * br[h]   (rank-1 bias correction; zero if br==0)
// ---------------------------------------------------------------------------
__global__ void __launch_bounds__(256) matvec_k(
    const float* __restrict__ W, const float* __restrict__ b,
    float* __restrict__ v, int H)
{
    const float* row = W + (size_t)blockIdx.x * H;
    int t = threadIdx.x;
    float p = 0.f;
    for (int h = t * 4; h < H; h += 1024) {
        float4 wv = *reinterpret_cast<const float4*>(row + h);
        float4 bv = *reinterpret_cast<const float4*>(b + h);
        p = fmaf(wv.x, bv.x, p); p = fmaf(wv.y, bv.y, p);
        p = fmaf(wv.z, bv.z, p); p = fmaf(wv.w, bv.w, p);
    }
    __shared__ float red[8];
    #pragma unroll
    for (int o = 16; o; o >>= 1) p += __shfl_xor_sync(0xffffffffu, p, o);
    if ((t & 31) == 0) red[t >> 5] = p;
    __syncthreads();
    if (t == 0) {
        float s = 0.f;
        #pragma unroll
        for (int i = 0; i < 8; i++) s += red[i];
        v[blockIdx.x] = s;
    }
}

// qv[i] = sum_d qe[i,d] * v[d],  i over B*T rows
__global__ void __launch_bounds__(256) rowdot_k(
    const float* __restrict__ qe, const float* __restrict__ v,
    float* __restrict__ qv)
{
    const float* row = qe + (size_t)blockIdx.x * DD;
    int t = threadIdx.x;
    float4 a = *reinterpret_cast<const float4*>(row + t * 4);
    float4 b = *reinterpret_cast<const float4*>(v + t * 4);
    float p = a.x * b.x + a.y * b.y + a.z * b.z + a.w * b.w;
    __shared__ float red[8];
    #pragma unroll
    for (int o = 16; o; o >>= 1) p += __shfl_xor_sync(0xffffffffu, p, o);
    if ((t & 31) == 0) red[t >> 5] = p;
    __syncthreads();
    if (t == 0) {
        float s = 0.f;
        #pragma unroll
        for (int i = 0; i < 8; i++) s += red[i];
        qv[blockIdx.x] = s;
    }
}

// ---------------------------------------------------------------------------
// Row softmax over T=512 (+ per-t additive offset qv) + 2-way bf16 split
// ---------------------------------------------------------------------------
__global__ void __launch_bounds__(256) softmax_split(
    const float* __restrict__ S, const float* __restrict__ qv,
    __nv_bfloat16* __restrict__ Ah, __nv_bfloat16* __restrict__ Al)
{
    const float* row = S + (size_t)blockIdx.x * TT;
    const float* qvb = qv + (blockIdx.x / RR) * TT;
    int t = threadIdx.x;
    float v0 = row[t] + qvb[t];
    float v1 = row[t + 256] + qvb[t + 256];

    __shared__ float red[8];

    float m = fmaxf(v0, v1);
    #pragma unroll
    for (int o = 16; o; o >>= 1) m = fmaxf(m, __shfl_xor_sync(0xffffffffu, m, o));
    if ((t & 31) == 0) red[t >> 5] = m;
    __syncthreads();
    if (t == 0) {
        float x = red[0];
        #pragma unroll
        for (int i = 1; i < 8; i++) x = fmaxf(x, red[i]);
        red[0] = x;
    }
    __syncthreads();
    m = red[0];

    float e0 = expf(v0 - m);
    float e1 = expf(v1 - m);
    float s = e0 + e1;
    #pragma unroll
    for (int o = 16; o; o >>= 1) s += __shfl_xor_sync(0xffffffffu, s, o);
    __syncthreads();
    if ((t & 31) == 0) red[t >> 5] = s;
    __syncthreads();
    if (t == 0) {
        float x = 0.f;
        #pragma unroll
        for (int i = 0; i < 8; i++) x += red[i];
        red[0] = x;
    }
    __syncthreads();
    float inv = 1.0f / red[0];
    size_t base = (size_t)blockIdx.x * TT;

    float a0 = e0 * inv;
    __nv_bfloat16 h0 = __float2bfloat16(a0);
    Ah[base + t] = h0;
    Al[base + t] = __float2bfloat16(a0 - __bfloat162float(h0));

    float a1 = e1 * inv;
    __nv_bfloat16 h1 = __float2bfloat16(a1);
    Ah[base + t + 256] = h1;
    Al[base + t + 256] = __float2bfloat16(a1 - __bfloat162float(h1));
}

// ---------------------------------------------------------------------------
// Final: out[b,r] = sum_d rf*Ws0 + att*Ws1 + rf*att*Ws2  (+bs)
// ---------------------------------------------------------------------------
__global__ void __launch_bounds__(256) final_out(
    const float* __restrict__ rf, const float* __restrict__ att,
    const float* __restrict__ Ws, const float* __restrict__ bs,
    float* __restrict__ out)
{
    size_t row = blockIdx.x;
    const float4* r4 = reinterpret_cast<const float4*>(rf + row * DD);
    const float4* a4 = reinterpret_cast<const float4*>(att + row * DD);
    int t = threadIdx.x;
    float4 rv = r4[t], av = a4[t];
    int d = t * 4;
    float p = 0.f;
    p = fmaf(rv.x, Ws[d + 0], p); p = fmaf(av.x, Ws[DD + d + 0], p); p = fmaf(rv.x * av.x, Ws[2 * DD + d + 0], p);
    p = fmaf(rv.y, Ws[d + 1], p); p = fmaf(av.y, Ws[DD + d + 1], p); p = fmaf(rv.y * av.y, Ws[2 * DD + d + 1], p);
    p = fmaf(rv.z, Ws[d + 2], p); p = fmaf(av.z, Ws[DD + d + 2], p); p = fmaf(rv.z * av.z, Ws[2 * DD + d + 2], p);
    p = fmaf(rv.w, Ws[d + 3], p); p = fmaf(av.w, Ws[DD + d + 3], p); p = fmaf(rv.w * av.w, Ws[2 * DD + d + 3], p);

    __shared__ float red[8];
    #pragma unroll
    for (int o = 16; o; o >>= 1) p += __shfl_xor_sync(0xffffffffu, p, o);
    if ((t & 31) == 0) red[t >> 5] = p;
    __syncthreads();
    if (t == 0) {
        float s = 0.f;
        #pragma unroll
        for (int i = 0; i < 8; i++) s += red[i];
        out[row] = s + bs[0];
    }
}

// ---------------------------------------------------------------------------
extern "C" void kernel_launch(void* const* d_in, const int* in_sizes, int n_in,
                              void* d_out, int out_size)
{
    const float* region = (const float*)d_in[0];
    const float* query  = (const float*)d_in[1];
    const float* Wr     = (const float*)d_in[2];
    const float* br     = (const float*)d_in[3];
    const float* Wq     = (const float*)d_in[4];
    const float* bq     = (const float*)d_in[5];
    const float* Ws     = (const float*)d_in[6];
    const float* bs     = (const float*)d_in[7];
    float* out = (float*)d_out;

    __nv_bfloat16 *Wr_h, *Wr_l, *Wq_h, *Wq_l, *Mt_h, *Mt_l;
    __nv_bfloat16 *rf_h, *rf_l, *qe_h, *qe_l, *P_h, *P_l;
    __nv_bfloat16 *attn_h, *attn_l, *qeT_h, *qeT_l;
    float *scores, *att, *v, *qv;
    cudaGetSymbolAddress((void**)&Wr_h, g_Wr_h);
    cudaGetSymbolAddress((void**)&Wr_l, g_Wr_l);
    cudaGetSymbolAddress((void**)&Wq_h, g_Wq_h);
    cudaGetSymbolAddress((void**)&Wq_l, g_Wq_l);
    cudaGetSymbolAddress((void**)&Mt_h, g_Mt_h);
    cudaGetSymbolAddress((void**)&Mt_l, g_Mt_l);
    cudaGetSymbolAddress((void**)&rf_h, g_rf_h);
    cudaGetSymbolAddress((void**)&rf_l, g_rf_l);
    cudaGetSymbolAddress((void**)&qe_h, g_qe_h);
    cudaGetSymbolAddress((void**)&qe_l, g_qe_l);
    cudaGetSymbolAddress((void**)&P_h, g_P_h);
    cudaGetSymbolAddress((void**)&P_l, g_P_l);
    cudaGetSymbolAddress((void**)&scores, g_scores);
    cudaGetSymbolAddress((void**)&attn_h, g_attn_h);
    cudaGetSymbolAddress((void**)&attn_l, g_attn_l);
    cudaGetSymbolAddress((void**)&qeT_h, g_qeT_h);
    cudaGetSymbolAddress((void**)&qeT_l, g_qeT_l);
    cudaGetSymbolAddress((void**)&att, g_att);
    cudaGetSymbolAddress((void**)&v, g_v);
    cudaGetSymbolAddress((void**)&qv, g_qv);

    const int SMEM = 2 * 4 * 16384;   // 131072
    cudaFuncSetAttribute(gemm_mma<true>,
                         cudaFuncAttributeMaxDynamicSharedMemorySize, SMEM);
    cudaFuncSetAttribute(gemm_mma<false>,
                         cudaFuncAttributeMaxDynamicSharedMemorySize, SMEM);

    // 1) splits of weights (already K-major) and activations
    split2_k<<<512, 256>>>((const float4*)Wr, Wr_h, Wr_l, DD * HH / 4);
    split2_k<<<512, 256>>>((const float4*)Wq, Wq_h, Wq_l, DD * HH / 4);
    split2_k<<<2048, 256>>>((const float4*)region, rf_h, rf_l,
                            (int)((size_t)BB * RR * DD / 4));
    split2_k<<<2048, 256>>>((const float4*)query, qe_h, qe_l,
                            (int)((size_t)BB * TT * DD / 4));
    // 2) Mt[e,d] = sum_h Wq[e,h] Wr[d,h]  (= (Wr@Wq^T)^T), split output
    gemm_mma<true><<<dim3(DD / 128, DD / 128, 1), 256, SMEM>>>(
        Wq_h, Wq_l, Wr_h, Wr_l, nullptr, Mt_h, Mt_l, nullptr,
        HH, 0, 0, 0, DD);
    // 3) P = rf @ M  (B operand = Mt, K-major), split output
    gemm_mma<true><<<dim3(DD / 128, (BB * RR) / 128, 1), 256, SMEM>>>(
        rf_h, rf_l, Mt_h, Mt_l, nullptr, P_h, P_l, nullptr,
        DD, 0, 0, 0, DD);
    // 4) rank-1 bias correction: v = Wq@br, qv[b,t] = qe.v
    matvec_k<<<DD, 256>>>(Wq, br, v, HH);
    rowdot_k<<<BB * TT, 256>>>(query, v, qv);
    // 5) scores = P @ qe^T (batched NT)
    gemm_mma<false><<<dim3(TT / 128, RR / 128, BB), 256, SMEM>>>(
        P_h, P_l, qe_h, qe_l, scores, nullptr, nullptr, nullptr,
        DD, (size_t)RR * DD, (size_t)TT * DD, (size_t)RR * TT, TT);
    // 6) softmax (+qv offset) + split of attn
    softmax_split<<<BB * RR, 256>>>(scores, qv, attn_h, attn_l);
    // 7) query transpose + split (B operand of attend GEMM)
    tsplit2_k<<<dim3(DD / 32, TT / 32, BB), dim3(32, 8)>>>(query, qeT_h, qeT_l, TT, DD);
    // 8) attended = attn @ query (batched NT)
    gemm_mma<false><<<dim3(DD / 128, RR / 128, BB), 256, SMEM>>>(
        attn_h, attn_l, qeT_h, qeT_l, att, nullptr, nullptr, nullptr,
        TT, (size_t)RR * TT, (size_t)DD * TT, (size_t)RR * DD, DD);
    // 9) final fused elementwise + reduce
    final_out<<<BB * RR, 256>>>(region, att, Ws, bs, out);
}

// round 5
// speedup vs baseline: 7.1504x; 1.2272x over previous
#include <cuda_runtime.h>
#include <cuda_bf16.h>

#define BB 16
#define RR 1024
#define TT 512
#define DD 1024
#define HH 1024

// ---------------------------------------------------------------------------
// Scratch (device globals — allocations are forbidden)
// ---------------------------------------------------------------------------
__device__ __nv_bfloat16 g_Wr_h[DD * HH], g_Wr_l[DD * HH];
__device__ __nv_bfloat16 g_Wq_h[DD * HH], g_Wq_l[DD * HH];
__device__ __nv_bfloat16 g_M2_h[DD * DD], g_M2_l[DD * DD];       // M2[d,e] = sum_h Wr[d,h]Wq[e,h]
__device__ __nv_bfloat16 g_rf_h[(size_t)BB * RR * DD], g_rf_l[(size_t)BB * RR * DD];
__device__ __nv_bfloat16 g_qe_h[(size_t)BB * TT * DD], g_qe_l[(size_t)BB * TT * DD];
__device__ __nv_bfloat16 g_Nt_h[(size_t)BB * TT * DD], g_Nt_l[(size_t)BB * TT * DD]; // Nt[b][t,d]
__device__ float         g_scores[(size_t)BB * RR * TT];
__device__ __nv_bfloat16 g_attn_h[(size_t)BB * RR * TT], g_attn_l[(size_t)BB * RR * TT];
__device__ __nv_bfloat16 g_qeT_h[(size_t)BB * DD * TT], g_qeT_l[(size_t)BB * DD * TT];
__device__ float         g_part[(size_t)BB * RR * 8];
__device__ float         g_v[DD];
__device__ float         g_qv[BB * TT];

// ---------------------------------------------------------------------------
// PTX helpers (sm_80-level features only: ldmatrix, cp.async, mma.sync)
// ---------------------------------------------------------------------------
__device__ __forceinline__ unsigned smem_u32(const void* p) {
    unsigned a;
    asm("{ .reg .u64 t; cvta.to.shared.u64 t, %1; cvt.u32.u64 %0, t; }" : "=r"(a) : "l"(p));
    return a;
}

#define CP_ASYNC16(dst, src) \
    asm volatile("cp.async.cg.shared.global [%0], [%1], 16;" :: "r"(dst), "l"(src))
#define CP_COMMIT() asm volatile("cp.async.commit_group;" ::: "memory")
#define CP_WAIT0()  asm volatile("cp.async.wait_group 0;" ::: "memory")
#define CP_WAIT1()  asm volatile("cp.async.wait_group 1;" ::: "memory")

__device__ __forceinline__ void ldsm4(unsigned* r, unsigned addr) {
    asm volatile("ldmatrix.sync.aligned.m8n8.x4.shared.b16 {%0,%1,%2,%3}, [%4];"
                 : "=r"(r[0]), "=r"(r[1]), "=r"(r[2]), "=r"(r[3]) : "r"(addr));
}

__device__ __forceinline__ void mma_bf16(float* c, const unsigned* a, const unsigned* b) {
    asm volatile(
        "mma.sync.aligned.m16n8k16.row.col.f32.bf16.bf16.f32 "
        "{%0,%1,%2,%3}, {%4,%5,%6,%7}, {%8,%9}, {%0,%1,%2,%3};"
        : "+f"(c[0]), "+f"(c[1]), "+f"(c[2]), "+f"(c[3])
        : "r"(a[0]), "r"(a[1]), "r"(a[2]), "r"(a[3]), "r"(b[0]), "r"(b[1]));
}

__device__ __forceinline__ unsigned swz(unsigned off) {
    return off ^ ((off >> 3) & 0x70);
}

// ---------------------------------------------------------------------------
// Split-bf16 tensor-core GEMM:  C[m,n] = sum_k A[m,k]*B[n,k]
// 3 terms: hh + hl + lh. CTA tile 128x128, K chunks of 64 bf16 (SW128),
// double-buffered cp.async. 8 warps (4M x 2N), warp tile 32x64.
// MODE 0: fp32 C.  MODE 1: split hi/lo bf16 C.  MODE 2: fused final scorer —
//   p = sum_n rf*Ws0 + C*Ws1 + rf*C*Ws2 over this CTA's n-slice, one partial
//   per (row, blockIdx.x) written to part[].
// ---------------------------------------------------------------------------
template <int MODE>
__global__ void __launch_bounds__(256) gemm_mma(
    const __nv_bfloat16* __restrict__ A0, const __nv_bfloat16* __restrict__ A1,
    const __nv_bfloat16* __restrict__ B0, const __nv_bfloat16* __restrict__ B1,
    float* __restrict__ Cf, __nv_bfloat16* __restrict__ Ch,
    __nv_bfloat16* __restrict__ Cl,
    const float* __restrict__ rfp, const float* __restrict__ Ws,
    float* __restrict__ part,
    int K, size_t sA, size_t sB, size_t sC, int ldc)
{
    constexpr unsigned TILE = 128 * 64 * 2;   // 16 KB per operand tile
    constexpr unsigned STAGE = 4 * TILE;      // Ah, Al, Bh, Bl

    extern __shared__ char smem[];
    const unsigned sbase = smem_u32(smem);

    const int tid = threadIdx.x;
    const int lid = tid & 31;
    const int wid = tid >> 5;
    const int wm = wid & 3;        // M slab (32 rows)
    const int wn = wid >> 2;       // N slab (64 cols)

    const size_t zb = blockIdx.z;
    const __nv_bfloat16* AP[2] = { A0 + zb * sA, A1 + zb * sA };
    const __nv_bfloat16* BP[2] = { B0 + zb * sB, B1 + zb * sB };
    const size_t rm0 = (size_t)blockIdx.y * 128;
    const size_t rn0 = (size_t)blockIdx.x * 128;
    const int NC = K >> 6;

    float c[2][8][4] = {};

    const int al_r  = lid & 15;
    const int al_k  = (lid >> 4) & 1;
    const int bl_r  = (lid & 7) + ((lid >> 4) << 3);
    const int bl_k  = (lid >> 3) & 1;

    auto load_stage = [&](int st, int ck) {
        const unsigned sdst = sbase + (unsigned)st * STAGE;
        const int k0 = ck << 6;
        #pragma unroll
        for (int t4 = 0; t4 < 4; t4++) {
            const __nv_bfloat16* src = (t4 < 2) ? AP[t4] : BP[t4 - 2];
            const size_t r0 = (t4 < 2) ? rm0 : rn0;
            #pragma unroll
            for (int i = 0; i < 4; i++) {
                int idx = i * 256 + tid;
                int row = idx >> 3, g = idx & 7;
                const __nv_bfloat16* gs = src + (r0 + row) * (size_t)K + k0 + g * 8;
                unsigned d = sdst + (unsigned)t4 * TILE + swz((unsigned)(row * 128 + g * 16));
                CP_ASYNC16(d, gs);
            }
        }
    };

    load_stage(0, 0);
    CP_COMMIT();

    for (int ck = 0; ck < NC; ck++) {
        if (ck + 1 < NC) {
            load_stage((ck + 1) & 1, ck + 1);
            CP_COMMIT();
            CP_WAIT1();
        } else {
            CP_WAIT0();
        }
        __syncthreads();

        const unsigned sb2 = sbase + (unsigned)(ck & 1) * STAGE;
        #pragma unroll
        for (int ks = 0; ks < 4; ks++) {
            unsigned af[2][2][4];
            unsigned bf[2][8][2];
            #pragma unroll
            for (int sp = 0; sp < 2; sp++) {
                #pragma unroll
                for (int mt = 0; mt < 2; mt++) {
                    unsigned addr = sb2 + (unsigned)sp * TILE +
                        swz((unsigned)((wm * 32 + mt * 16 + al_r) * 128 + ks * 32 + al_k * 16));
                    ldsm4(af[sp][mt], addr);
                }
                #pragma unroll
                for (int np = 0; np < 4; np++) {
                    unsigned r[4];
                    unsigned addr = sb2 + (unsigned)(2 + sp) * TILE +
                        swz((unsigned)((wn * 64 + np * 16 + bl_r) * 128 + ks * 32 + bl_k * 16));
                    ldsm4(r, addr);
                    bf[sp][2 * np][0] = r[0]; bf[sp][2 * np][1] = r[1];
                    bf[sp][2 * np + 1][0] = r[2]; bf[sp][2 * np + 1][1] = r[3];
                }
            }
            // 3 terms: hh, hl, lh
            #pragma unroll
            for (int tm = 0; tm < 3; tm++) {
                const int i = (tm == 2) ? 1 : 0;
                const int j = (tm == 1) ? 1 : 0;
                #pragma unroll
                for (int mt = 0; mt < 2; mt++)
                    #pragma unroll
                    for (int nt = 0; nt < 8; nt++)
                        mma_bf16(c[mt][nt], af[i][mt], bf[j][nt]);
            }
        }
        __syncthreads();
    }

    const int qr = lid >> 2;
    const int qc = (lid & 3) * 2;

    if (MODE == 2) {
        // Fused final: partial dot over this CTA's 128-column d-slice.
        float p[2][2] = {};
        #pragma unroll
        for (int mt = 0; mt < 2; mt++) {
            #pragma unroll
            for (int nt = 0; nt < 8; nt++) {
                int gc = (int)rn0 + wn * 64 + nt * 8 + qc;
                float w0a = Ws[gc],          w0b = Ws[gc + 1];
                float w1a = Ws[DD + gc],     w1b = Ws[DD + gc + 1];
                float w2a = Ws[2 * DD + gc], w2b = Ws[2 * DD + gc + 1];
                #pragma unroll
                for (int half = 0; half < 2; half++) {
                    size_t row = rm0 + wm * 32 + mt * 16 + qr + half * 8;
                    float2 rv = *reinterpret_cast<const float2*>(
                        rfp + (zb * RR + row) * (size_t)DD + gc);
                    float a0 = c[mt][nt][2 * half], a1 = c[mt][nt][2 * half + 1];
                    float acc = p[mt][half];
                    acc = fmaf(rv.x, w0a, acc);
                    acc = fmaf(a0, w1a, acc);
                    acc = fmaf(rv.x * a0, w2a, acc);
                    acc = fmaf(rv.y, w0b, acc);
                    acc = fmaf(a1, w1b, acc);
                    acc = fmaf(rv.y * a1, w2b, acc);
                    p[mt][half] = acc;
                }
            }
        }
        float* sp = reinterpret_cast<float*>(smem);   // [128][2]
        #pragma unroll
        for (int mt = 0; mt < 2; mt++)
            #pragma unroll
            for (int half = 0; half < 2; half++) {
                float v = p[mt][half];
                v += __shfl_xor_sync(0xffffffffu, v, 1);
                v += __shfl_xor_sync(0xffffffffu, v, 2);
                if ((lid & 3) == 0) {
                    int lr = wm * 32 + mt * 16 + qr + half * 8;
                    sp[lr * 2 + wn] = v;
                }
            }
        __syncthreads();
        if (tid < 128) {
            part[(zb * RR + rm0 + tid) * 8 + blockIdx.x] =
                sp[tid * 2] + sp[tid * 2 + 1];
        }
        return;
    }

    #pragma unroll
    for (int mt = 0; mt < 2; mt++) {
        #pragma unroll
        for (int nt = 0; nt < 8; nt++) {
            size_t gr = rm0 + wm * 32 + mt * 16 + qr;
            int gc = (int)rn0 + wn * 64 + nt * 8 + qc;
            if (MODE == 1) {
                #pragma unroll
                for (int half = 0; half < 2; half++) {
                    float v0 = c[mt][nt][2 * half + 0];
                    float v1 = c[mt][nt][2 * half + 1];
                    size_t o = zb * sC + (gr + half * 8) * (size_t)ldc + gc;
                    __nv_bfloat162 hv, lv;
                    hv.x = __float2bfloat16(v0);
                    hv.y = __float2bfloat16(v1);
                    lv.x = __float2bfloat16(v0 - __bfloat162float(hv.x));
                    lv.y = __float2bfloat16(v1 - __bfloat162float(hv.y));
                    *reinterpret_cast<__nv_bfloat162*>(Ch + o) = hv;
                    *reinterpret_cast<__nv_bfloat162*>(Cl + o) = lv;
                }
            } else {
                #pragma unroll
                for (int half = 0; half < 2; half++) {
                    size_t o = zb * sC + (gr + half * 8) * (size_t)ldc + gc;
                    float2 v = make_float2(c[mt][nt][2 * half], c[mt][nt][2 * half + 1]);
                    *reinterpret_cast<float2*>(Cf + o) = v;
                }
            }
        }
    }
}

// ---------------------------------------------------------------------------
// fp32 -> 2-way bf16 split (elementwise, vectorized)
// ---------------------------------------------------------------------------
__global__ void __launch_bounds__(256) split2_k(
    const float4* __restrict__ x, __nv_bfloat16* __restrict__ h,
    __nv_bfloat16* __restrict__ l, int n4)
{
    for (int i = blockIdx.x * blockDim.x + threadIdx.x; i < n4;
         i += gridDim.x * blockDim.x) {
        float4 v = x[i];
        float a[4] = {v.x, v.y, v.z, v.w};
        __nv_bfloat16 hh[4], ll[4];
        #pragma unroll
        for (int k = 0; k < 4; k++) {
            hh[k] = __float2bfloat16(a[k]);
            ll[k] = __float2bfloat16(a[k] - __bfloat162float(hh[k]));
        }
        __nv_bfloat162 p0, p1;
        p0.x = hh[0]; p0.y = hh[1]; p1.x = hh[2]; p1.y = hh[3];
        reinterpret_cast<__nv_bfloat162*>(h)[2 * i] = p0;
        reinterpret_cast<__nv_bfloat162*>(h)[2 * i + 1] = p1;
        p0.x = ll[0]; p0.y = ll[1]; p1.x = ll[2]; p1.y = ll[3];
        reinterpret_cast<__nv_bfloat162*>(l)[2 * i] = p0;
        reinterpret_cast<__nv_bfloat162*>(l)[2 * i + 1] = p1;
    }
}

// ---------------------------------------------------------------------------
// Batched transpose + 2-way split: src[b,rows,cols] -> dst[b,cols,rows]
// ---------------------------------------------------------------------------
__global__ void tsplit2_k(const float* __restrict__ src,
                          __nv_bfloat16* __restrict__ d0,
                          __nv_bfloat16* __restrict__ d1, int rows, int cols)
{
    __shared__ float tile[32][33];
    int b = blockIdx.z;
    const float* s = src + (size_t)b * rows * cols;
    int c0 = blockIdx.x * 32, r0 = blockIdx.y * 32;
    int tx = threadIdx.x, ty = threadIdx.y;
    #pragma unroll
    for (int k = 0; k < 32; k += 8)
        tile[ty + k][tx] = s[(size_t)(r0 + ty + k) * cols + c0 + tx];
    __syncthreads();
    size_t dbase = (size_t)b * rows * cols;
    #pragma unroll
    for (int k = 0; k < 32; k += 8) {
        int oc = c0 + ty + k;
        float v = tile[tx][ty + k];
        size_t o = dbase + (size_t)oc * rows + r0 + tx;
        __nv_bfloat16 h = __float2bfloat16(v);
        d0[o] = h;
        d1[o] = __float2bfloat16(v - __bfloat162float(h));
    }
}

// ---------------------------------------------------------------------------
// v[d] = sum_h Wq[d,h] * br[h]   (rank-1 bias correction; zero if br==0)
// ---------------------------------------------------------------------------
__global__ void __launch_bounds__(256) matvec_k(
    const float* __restrict__ W, const float* __restrict__ b,
    float* __restrict__ v, int H)
{
    const float* row = W + (size_t)blockIdx.x * H;
    int t = threadIdx.x;
    float p = 0.f;
    for (int h = t * 4; h < H; h += 1024) {
        float4 wv = *reinterpret_cast<const float4*>(row + h);
        float4 bv = *reinterpret_cast<const float4*>(b + h);
        p = fmaf(wv.x, bv.x, p); p = fmaf(wv.y, bv.y, p);
        p = fmaf(wv.z, bv.z, p); p = fmaf(wv.w, bv.w, p);
    }
    __shared__ float red[8];
    #pragma unroll
    for (int o = 16; o; o >>= 1) p += __shfl_xor_sync(0xffffffffu, p, o);
    if ((t & 31) == 0) red[t >> 5] = p;
    __syncthreads();
    if (t == 0) {
        float s = 0.f;
        #pragma unroll
        for (int i = 0; i < 8; i++) s += red[i];
        v[blockIdx.x] = s;
    }
}

// qv[i] = sum_d qe[i,d] * v[d],  i over B*T rows
__global__ void __launch_bounds__(256) rowdot_k(
    const float* __restrict__ qe, const float* __restrict__ v,
    float* __restrict__ qv)
{
    const float* row = qe + (size_t)blockIdx.x * DD;
    int t = threadIdx.x;
    float4 a = *reinterpret_cast<const float4*>(row + t * 4);
    float4 b = *reinterpret_cast<const float4*>(v + t * 4);
    float p = a.x * b.x + a.y * b.y + a.z * b.z + a.w * b.w;
    __shared__ float red[8];
    #pragma unroll
    for (int o = 16; o; o >>= 1) p += __shfl_xor_sync(0xffffffffu, p, o);
    if ((t & 31) == 0) red[t >> 5] = p;
    __syncthreads();
    if (t == 0) {
        float s = 0.f;
        #pragma unroll
        for (int i = 0; i < 8; i++) s += red[i];
        qv[blockIdx.x] = s;
    }
}

// ---------------------------------------------------------------------------
// Row softmax over T=512 (+ per-t additive offset qv) + 2-way bf16 split
// ---------------------------------------------------------------------------
__global__ void __launch_bounds__(256) softmax_split(
    const float* __restrict__ S, const float* __restrict__ qv,
    __nv_bfloat16* __restrict__ Ah, __nv_bfloat16* __restrict__ Al)
{
    const float* row = S + (size_t)blockIdx.x * TT;
    const float* qvb = qv + (blockIdx.x / RR) * TT;
    int t = threadIdx.x;
    float v0 = row[t] + qvb[t];
    float v1 = row[t + 256] + qvb[t + 256];

    __shared__ float red[8];

    float m = fmaxf(v0, v1);
    #pragma unroll
    for (int o = 16; o; o >>= 1) m = fmaxf(m, __shfl_xor_sync(0xffffffffu, m, o));
    if ((t & 31) == 0) red[t >> 5] = m;
    __syncthreads();
    if (t == 0) {
        float x = red[0];
        #pragma unroll
        for (int i = 1; i < 8; i++) x = fmaxf(x, red[i]);
        red[0] = x;
    }
    __syncthreads();
    m = red[0];

    float e0 = expf(v0 - m);
    float e1 = expf(v1 - m);
    float s = e0 + e1;
    #pragma unroll
    for (int o = 16; o; o >>= 1) s += __shfl_xor_sync(0xffffffffu, s, o);
    __syncthreads();
    if ((t & 31) == 0) red[t >> 5] = s;
    __syncthreads();
    if (t == 0) {
        float x = 0.f;
        #pragma unroll
        for (int i = 0; i < 8; i++) x += red[i];
        red[0] = x;
    }
    __syncthreads();
    float inv = 1.0f / red[0];
    size_t base = (size_t)blockIdx.x * TT;

    float a0 = e0 * inv;
    __nv_bfloat16 h0 = __float2bfloat16(a0);
    Ah[base + t] = h0;
    Al[base + t] = __float2bfloat16(a0 - __bfloat162float(h0));

    float a1 = e1 * inv;
    __nv_bfloat16 h1 = __float2bfloat16(a1);
    Ah[base + t + 256] = h1;
    Al[base + t + 256] = __float2bfloat16(a1 - __bfloat162float(h1));
}

// ---------------------------------------------------------------------------
// out[i] = sum of 8 partials + bs
// ---------------------------------------------------------------------------
__global__ void __launch_bounds__(256) reduce8_k(
    const float* __restrict__ part, const float* __restrict__ bs,
    float* __restrict__ out)
{
    int i = blockIdx.x * 256 + threadIdx.x;
    const float4* p4 = reinterpret_cast<const float4*>(part + (size_t)i * 8);
    float4 a = p4[0], b = p4[1];
    out[i] = a.x + a.y + a.z + a.w + b.x + b.y + b.z + b.w + bs[0];
}

// ---------------------------------------------------------------------------
extern "C" void kernel_launch(void* const* d_in, const int* in_sizes, int n_in,
                              void* d_out, int out_size)
{
    const float* region = (const float*)d_in[0];
    const float* query  = (const float*)d_in[1];
    const float* Wr     = (const float*)d_in[2];
    const float* br     = (const float*)d_in[3];
    const float* Wq     = (const float*)d_in[4];
    const float* bq     = (const float*)d_in[5];
    const float* Ws     = (const float*)d_in[6];
    const float* bs     = (const float*)d_in[7];
    float* out = (float*)d_out;
    (void)bq;  // softmax-invariant terms drop out

    __nv_bfloat16 *Wr_h, *Wr_l, *Wq_h, *Wq_l, *M2_h, *M2_l;
    __nv_bfloat16 *rf_h, *rf_l, *qe_h, *qe_l, *Nt_h, *Nt_l;
    __nv_bfloat16 *attn_h, *attn_l, *qeT_h, *qeT_l;
    float *scores, *partb, *v, *qv;
    cudaGetSymbolAddress((void**)&Wr_h, g_Wr_h);
    cudaGetSymbolAddress((void**)&Wr_l, g_Wr_l);
    cudaGetSymbolAddress((void**)&Wq_h, g_Wq_h);
    cudaGetSymbolAddress((void**)&Wq_l, g_Wq_l);
    cudaGetSymbolAddress((void**)&M2_h, g_M2_h);
    cudaGetSymbolAddress((void**)&M2_l, g_M2_l);
    cudaGetSymbolAddress((void**)&rf_h, g_rf_h);
    cudaGetSymbolAddress((void**)&rf_l, g_rf_l);
    cudaGetSymbolAddress((void**)&qe_h, g_qe_h);
    cudaGetSymbolAddress((void**)&qe_l, g_qe_l);
    cudaGetSymbolAddress((void**)&Nt_h, g_Nt_h);
    cudaGetSymbolAddress((void**)&Nt_l, g_Nt_l);
    cudaGetSymbolAddress((void**)&scores, g_scores);
    cudaGetSymbolAddress((void**)&attn_h, g_attn_h);
    cudaGetSymbolAddress((void**)&attn_l, g_attn_l);
    cudaGetSymbolAddress((void**)&qeT_h, g_qeT_h);
    cudaGetSymbolAddress((void**)&qeT_l, g_qeT_l);
    cudaGetSymbolAddress((void**)&partb, g_part);
    cudaGetSymbolAddress((void**)&v, g_v);
    cudaGetSymbolAddress((void**)&qv, g_qv);

    const int SMEM = 2 * 4 * 16384;   // 131072
    cudaFuncSetAttribute(gemm_mma<0>, cudaFuncAttributeMaxDynamicSharedMemorySize, SMEM);
    cudaFuncSetAttribute(gemm_mma<1>, cudaFuncAttributeMaxDynamicSharedMemorySize, SMEM);
    cudaFuncSetAttribute(gemm_mma<2>, cudaFuncAttributeMaxDynamicSharedMemorySize, SMEM);

    // 1) splits of weights (K-major over h) and activations
    split2_k<<<512, 256>>>((const float4*)Wr, Wr_h, Wr_l, DD * HH / 4);
    split2_k<<<512, 256>>>((const float4*)Wq, Wq_h, Wq_l, DD * HH / 4);
    split2_k<<<2048, 256>>>((const float4*)region, rf_h, rf_l,
                            (int)((size_t)BB * RR * DD / 4));
    split2_k<<<2048, 256>>>((const float4*)query, qe_h, qe_l,
                            (int)((size_t)BB * TT * DD / 4));
    // 2) M2[d,e] = sum_h Wr[d,h] Wq[e,h]  (e contiguous), split output
    gemm_mma<1><<<dim3(DD / 128, DD / 128, 1), 256, SMEM>>>(
        Wr_h, Wr_l, Wq_h, Wq_l, nullptr, M2_h, M2_l,
        nullptr, nullptr, nullptr, HH, 0, 0, 0, DD);
    // 3) Nt[b][t,d] = sum_e qe[b,t,e] M2[d,e]  (d contiguous), split output
    gemm_mma<1><<<dim3(DD / 128, TT / 128, BB), 256, SMEM>>>(
        qe_h, qe_l, M2_h, M2_l, nullptr, Nt_h, Nt_l,
        nullptr, nullptr, nullptr,
        DD, (size_t)TT * DD, 0, (size_t)TT * DD, DD);
    // 4) rank-1 bias correction: v = Wq@br, qv[b,t] = qe.v
    matvec_k<<<DD, 256>>>(Wq, br, v, HH);
    rowdot_k<<<BB * TT, 256>>>(query, v, qv);
    // 5) scores[b][r,t] = sum_d rf[b,r,d] Nt[b][t,d]  (batched NT)
    gemm_mma<0><<<dim3(TT / 128, RR / 128, BB), 256, SMEM>>>(
        rf_h, rf_l, Nt_h, Nt_l, scores, nullptr, nullptr,
        nullptr, nullptr, nullptr,
        DD, (size_t)RR * DD, (size_t)TT * DD, (size_t)RR * TT, TT);
    // 6) softmax (+qv offset) + split of attn
    softmax_split<<<BB * RR, 256>>>(scores, qv, attn_h, attn_l);
    // 7) query transpose + split (B operand of attend GEMM)
    tsplit2_k<<<dim3(DD / 32, TT / 32, BB), dim3(32, 8)>>>(query, qeT_h, qeT_l, TT, DD);
    // 8) attended GEMM with fused final-scorer epilogue -> partials
    gemm_mma<2><<<dim3(DD / 128, RR / 128, BB), 256, SMEM>>>(
        attn_h, attn_l, qeT_h, qeT_l, nullptr, nullptr, nullptr,
        region, Ws, partb,
        TT, (size_t)RR * TT, (size_t)DD * TT, 0, 0);
    // 9) out = sum of 8 partials + bs
    reduce8_k<<<BB * RR / 256, 256>>>(partb, bs, out);
}